// round 10
// baseline (speedup 1.0000x reference)
#include <cuda_runtime.h>
#include <math.h>

#define BB 32
#define SS 2048
#define DD 1024
#define ROWS 16
#define CHUNKS (SS / ROWS)      // 128 blocks per batch
#define NBLK (BB * CHUNKS)      // 4096 blocks total
#define BETA_F 0.1f
#define RHO_F 1.0f

// Deterministic per-block partials (no float atomics -> bitwise stable across replays)
__device__ float g_p1[NBLK];
__device__ float g_p2[NBLK];
__device__ unsigned int g_count = 0;   // last-block ticket; self-resets each launch

// __launch_bounds__(256, 8): cap regs at 32 -> 8 CTAs/SM (R6 measured occ=97.5%).
// Handshake (store+fence+ticket) lives in thread 0 ONLY — R9 measured this
// exact single-thread pattern at full 6.97 TB/s; R6's regression came from
// issuing the GPU-scope MEMBAR from all 256 threads per block.
__global__ void __launch_bounds__(256, 8) wdpo_fused(const float* __restrict__ e1,
                                                     const float* __restrict__ e2,
                                                     const float* __restrict__ w,
                                                     const float* __restrict__ lp1ref,
                                                     const float* __restrict__ lp2ref,
                                                     const float* __restrict__ pref,
                                                     float* __restrict__ out) {
    const int t   = threadIdx.x;            // 0..255, owns a float4 column group
    const int blk = blockIdx.x;
    const int b     = blk >> 7;             // / CHUNKS
    const int chunk = blk & (CHUNKS - 1);
    const int lane = t & 31, wid = t >> 5;

    // each thread keeps its 4 w values in registers for the whole block
    const float4 w4 = reinterpret_cast<const float4*>(w)[t];

    const size_t base = ((size_t)b * SS + (size_t)chunk * ROWS) * DD + 4 * (size_t)t;
    const float4* __restrict__ p1 = reinterpret_cast<const float4*>(e1 + base);
    const float4* __restrict__ p2 = reinterpret_cast<const float4*>(e2 + base);

    // R3/R7 loop body verbatim — measured 6.97 TB/s
    float s1 = 0.f, s2 = 0.f;
#pragma unroll 8
    for (int r = 0; r < ROWS; r++) {
        const float4 a = p1[(size_t)r * (DD / 4)];
        const float4 c = p2[(size_t)r * (DD / 4)];
        s1 += a.x * w4.x + a.y * w4.y + a.z * w4.z + a.w * w4.w;
        s2 += c.x * w4.x + c.y * w4.y + c.z * w4.z + c.w * w4.w;
    }

    // block reduction: warp shuffle then 8-warp shared fold
    __shared__ float sh1[8], sh2[8];
    __shared__ int s_last;
#pragma unroll
    for (int o = 16; o; o >>= 1) {
        s1 += __shfl_down_sync(0xffffffffu, s1, o);
        s2 += __shfl_down_sync(0xffffffffu, s2, o);
    }
    if (lane == 0) { sh1[wid] = s1; sh2[wid] = s2; }
    __syncthreads();
    if (wid == 0) {
        s1 = (lane < 8) ? sh1[lane] : 0.f;
        s2 = (lane < 8) ? sh2[lane] : 0.f;
#pragma unroll
        for (int o = 4; o; o >>= 1) {
            s1 += __shfl_down_sync(0xffffffffu, s1, o);
            s2 += __shfl_down_sync(0xffffffffu, s2, o);
        }
        if (lane == 0) {
            // single-thread release + ticket (the R9-measured-fast pattern)
            g_p1[blk] = s1;
            g_p2[blk] = s2;
            __threadfence();
            unsigned int prev = atomicAdd(&g_count, 1u);
            s_last = (prev == NBLK - 1u) ? 1 : 0;
        }
    }
    __syncthreads();
    if (!s_last) return;

    // ---- this block is last: fold all partials + scalar epilogue (runs once) ----
    __shared__ float s_ind[BB];
    __shared__ float s_gns[BB];
    __shared__ float s_wsq;

    __threadfence();   // acquire side for partials (pairs with writers' release)

    // ||w||^2 : this block's w4 registers cover all of D
    {
        float v = w4.x * w4.x + w4.y * w4.y + w4.z * w4.z + w4.w * w4.w;
#pragma unroll
        for (int o = 16; o; o >>= 1) v += __shfl_down_sync(0xffffffffu, v, o);
        if (lane == 0) sh1[wid] = v;         // reuse sh1
        __syncthreads();
        if (t == 0) {
            float a = 0.f;
#pragma unroll
            for (int i = 0; i < 8; i++) a += sh1[i];
            s_wsq = a;
        }
        __syncthreads();
    }
    const float wsq = s_wsq;

    // warp `wid` folds batches wid*4 .. wid*4+3 (fixed order -> deterministic)
#pragma unroll
    for (int j = 0; j < 4; j++) {
        const int bb = wid * 4 + j;
        const int pb = bb * CHUNKS;
        float a1 = __ldcg(&g_p1[pb + lane])       + __ldcg(&g_p1[pb + lane + 32]) +
                   __ldcg(&g_p1[pb + lane + 64])  + __ldcg(&g_p1[pb + lane + 96]);
        float a2 = __ldcg(&g_p2[pb + lane])       + __ldcg(&g_p2[pb + lane + 32]) +
                   __ldcg(&g_p2[pb + lane + 64])  + __ldcg(&g_p2[pb + lane + 96]);
#pragma unroll
        for (int o = 16; o; o >>= 1) {
            a1 += __shfl_down_sync(0xffffffffu, a1, o);
            a2 += __shfl_down_sync(0xffffffffu, a2, o);
        }
        if (lane == 0) {
            const float h = (a1 - lp1ref[bb]) - (a2 - lp2ref[bb]);
            const float z = BETA_F * h;
            const float p = pref[bb];
            // stable softplus: softplus(x) = max(x,0) + log1p(exp(-|x|))
            const float lp = log1pf(expf(-fabsf(z)));
            const float sp_pos = fmaxf(z, 0.f) + lp;   // softplus(z)  = l2
            const float sp_neg = fmaxf(-z, 0.f) + lp;  // softplus(-z) = l1
            const float ind = p * sp_neg + (1.f - p) * sp_pos;
            const float sig = 1.f / (1.f + expf(-z));
            const float c = BETA_F * (sig - p);
            s_ind[bb] = ind;
            s_gns[bb] = 2.f * (float)SS * wsq * c * c;
        }
    }
    __syncthreads();
    if (wid == 0) {
        float i = s_ind[lane];
        float g = s_gns[lane];
#pragma unroll
        for (int o = 16; o; o >>= 1) {
            i += __shfl_down_sync(0xffffffffu, i, o);
            g += __shfl_down_sync(0xffffffffu, g, o);
        }
        if (lane == 0) {
            out[0] = i * (1.f / (float)BB) + RHO_F * sqrtf(g * (1.f / (float)BB));
            g_count = 0;                     // reset ticket for next graph replay
        }
    }
}

extern "C" void kernel_launch(void* const* d_in, const int* in_sizes, int n_in,
                              void* d_out, int out_size) {
    const float* e1     = (const float*)d_in[0];  // emb_a1 (B,S,D)
    const float* e2     = (const float*)d_in[1];  // emb_a2 (B,S,D)
    const float* w      = (const float*)d_in[2];  // w (D,)
    const float* lp1ref = (const float*)d_in[3];  // log_prob_a1_ref (B,)
    const float* lp2ref = (const float*)d_in[4];  // log_prob_a2_ref (B,)
    const float* pref   = (const float*)d_in[5];  // preference (B,)
    float* out          = (float*)d_out;

    wdpo_fused<<<NBLK, 256>>>(e1, e2, w, lp1ref, lp2ref, pref, out);
}

// round 12
// speedup vs baseline: 1.0260x; 1.0260x over previous
#include <cuda_runtime.h>
#include <math.h>

#define BB 32
#define SS 2048
#define DD 1024
#define ROWS 64
#define CHUNKS (SS / ROWS)      // 32 blocks per batch
#define NBLK (BB * CHUNKS)      // 1024 blocks total
#define BETA_F 0.1f
#define RHO_F 1.0f

// Deterministic per-block partials, packed: .x = <e1,w>, .y = <e2,w>
__device__ float2 g_p[NBLK];
__device__ float  g_wsq;        // ||w||^2, produced by reduce block 0

// ---------------- hot streaming kernel (R8 shape, measured ~6.9 TB/s) ---------
__global__ void __launch_bounds__(256) wdpo_reduce(const float* __restrict__ e1,
                                                   const float* __restrict__ e2,
                                                   const float* __restrict__ w) {
    const int t   = threadIdx.x;            // 0..255, owns float4 column group
    const int blk = blockIdx.x;
    const int b     = blk >> 5;             // / CHUNKS
    const int chunk = blk & (CHUNKS - 1);

    // each thread keeps its 4 w values in registers for the whole block
    const float4 w4 = reinterpret_cast<const float4*>(w)[t];

    const size_t base = ((size_t)b * SS + (size_t)chunk * ROWS) * DD + 4 * (size_t)t;
    const float4* __restrict__ p1 = reinterpret_cast<const float4*>(e1 + base);
    const float4* __restrict__ p2 = reinterpret_cast<const float4*>(e2 + base);

    float s1 = 0.f, s2 = 0.f;
#pragma unroll 8
    for (int r = 0; r < ROWS; r++) {
        const float4 a = p1[(size_t)r * (DD / 4)];
        const float4 c = p2[(size_t)r * (DD / 4)];
        s1 += a.x * w4.x + a.y * w4.y + a.z * w4.z + a.w * w4.w;
        s2 += c.x * w4.x + c.y * w4.y + c.z * w4.z + c.w * w4.w;
    }

    // block reduction: warp shuffle then 8-warp shared fold
    __shared__ float sh1[8], sh2[8];
#pragma unroll
    for (int o = 16; o; o >>= 1) {
        s1 += __shfl_down_sync(0xffffffffu, s1, o);
        s2 += __shfl_down_sync(0xffffffffu, s2, o);
    }
    const int lane = t & 31, wid = t >> 5;
    if (lane == 0) { sh1[wid] = s1; sh2[wid] = s2; }
    __syncthreads();
    if (wid == 0) {
        s1 = (lane < 8) ? sh1[lane] : 0.f;
        s2 = (lane < 8) ? sh2[lane] : 0.f;
#pragma unroll
        for (int o = 4; o; o >>= 1) {
            s1 += __shfl_down_sync(0xffffffffu, s1, o);
            s2 += __shfl_down_sync(0xffffffffu, s2, o);
        }
        if (lane == 0) g_p[blk] = make_float2(s1, s2);
    }

    // Block 0 additionally produces ||w||^2 from its resident w4 registers —
    // zero extra global traffic, hidden behind the other 1023 blocks.
    if (blk == 0) {
        __syncthreads();                     // sh1 reuse safe
        float v = w4.x * w4.x + w4.y * w4.y + w4.z * w4.z + w4.w * w4.w;
#pragma unroll
        for (int o = 16; o; o >>= 1) v += __shfl_down_sync(0xffffffffu, v, o);
        if (lane == 0) sh1[wid] = v;
        __syncthreads();
        if (t == 0) {
            float a = 0.f;
#pragma unroll
            for (int i = 0; i < 8; i++) a += sh1[i];
            g_wsq = a;
        }
    }

    cudaTriggerProgrammaticLaunchCompletion();
}

// ---------------- minimal epilogue: 1 load/lane, 1 barrier ---------------------
__global__ void __launch_bounds__(1024) wdpo_epilogue(const float* __restrict__ lp1ref,
                                                      const float* __restrict__ lp2ref,
                                                      const float* __restrict__ pref,
                                                      float* __restrict__ out) {
    const int t = threadIdx.x;
    const int lane = t & 31, wid = t >> 5;

    __shared__ float s_ind[BB];
    __shared__ float s_c2[BB];

    cudaGridDependencySynchronize();        // partials + g_wsq ready

    // warp `wid` folds batch b = wid: exactly one float2 load per lane
    const int b = wid;
    const float2 pp = g_p[b * CHUNKS + lane];
    float s1 = pp.x, s2 = pp.y;
#pragma unroll
    for (int o = 16; o; o >>= 1) {
        s1 += __shfl_down_sync(0xffffffffu, s1, o);
        s2 += __shfl_down_sync(0xffffffffu, s2, o);
    }
    if (lane == 0) {
        const float h = (s1 - lp1ref[b]) - (s2 - lp2ref[b]);
        const float z = BETA_F * h;
        const float p = pref[b];
        // stable softplus: softplus(x) = max(x,0) + log1p(exp(-|x|))
        const float lp = log1pf(expf(-fabsf(z)));
        const float sp_pos = fmaxf(z, 0.f) + lp;   // softplus(z)  = l2
        const float sp_neg = fmaxf(-z, 0.f) + lp;  // softplus(-z) = l1
        s_ind[b] = p * sp_neg + (1.f - p) * sp_pos;
        const float sig = 1.f / (1.f + expf(-z));
        const float c = BETA_F * (sig - p);
        s_c2[b] = c * c;                            // wsq factored out
    }
    __syncthreads();
    if (wid == 0) {
        float i  = s_ind[lane];
        float c2 = s_c2[lane];
#pragma unroll
        for (int o = 16; o; o >>= 1) {
            i  += __shfl_down_sync(0xffffffffu, i, o);
            c2 += __shfl_down_sync(0xffffffffu, c2, o);
        }
        if (lane == 0) {
            const float wsq = g_wsq;
            // mean(gns) = 2*S*wsq*mean(c^2)
            out[0] = i * (1.f / (float)BB)
                   + RHO_F * sqrtf(2.f * (float)SS * wsq * c2 * (1.f / (float)BB));
        }
    }
}

extern "C" void kernel_launch(void* const* d_in, const int* in_sizes, int n_in,
                              void* d_out, int out_size) {
    const float* e1     = (const float*)d_in[0];  // emb_a1 (B,S,D)
    const float* e2     = (const float*)d_in[1];  // emb_a2 (B,S,D)
    const float* w      = (const float*)d_in[2];  // w (D,)
    const float* lp1ref = (const float*)d_in[3];  // log_prob_a1_ref (B,)
    const float* lp2ref = (const float*)d_in[4];  // log_prob_a2_ref (B,)
    const float* pref   = (const float*)d_in[5];  // preference (B,)
    float* out          = (float*)d_out;

    wdpo_reduce<<<NBLK, 256>>>(e1, e2, w);

    // PDL attr (free if honored; harmless if the graph drops it)
    cudaLaunchConfig_t cfg = {};
    cfg.gridDim  = dim3(1, 1, 1);
    cfg.blockDim = dim3(1024, 1, 1);
    cfg.dynamicSmemBytes = 0;
    cfg.stream = 0;
    cudaLaunchAttribute attr[1];
    attr[0].id = cudaLaunchAttributeProgrammaticStreamSerialization;
    attr[0].val.programmaticStreamSerializationAllowed = 1;
    cfg.attrs = attr;
    cfg.numAttrs = 1;
    cudaError_t err = cudaLaunchKernelEx(&cfg, wdpo_epilogue, lp1ref, lp2ref, pref, out);
    if (err != cudaSuccess) {
        wdpo_epilogue<<<1, 1024>>>(lp1ref, lp2ref, pref, out);
    }
}